// round 1
// baseline (speedup 1.0000x reference)
#include <cuda_runtime.h>
#include <cuda_bf16.h>

// ---------------------------------------------------------------------------
// LJ 12-6 over a neighbor list.
//   Inputs (metadata order): R[600000] f32, epsilon[1] f32, sigma[1] f32,
//                            cutoff[1] f32, idx_i[12.8M] i32, idx_j[12.8M] i32
//   Output: d_out[800000] f32 = energy[N] ++ forces[N*3]
//
// Strategy:
//   - R (2.4MB) fits in L2; pre-pack to float4 so every gather is one aligned
//     LDG.128 = one 32B L2 sector.
//   - Only ~2% of pairs are inside the cutoff -> skip the scatter for masked
//     pairs; atomic traffic is negligible (~1M REDG total).
//   - Accumulate {E, fx, fy, fz} per atom in a static __device__ float4 array
//     (no allocations), then a tiny writeout kernel reshapes into d_out.
// ---------------------------------------------------------------------------

#define MAX_ATOMS 200000

__device__ float4 g_acc[MAX_ATOMS];   // {E, fx, fy, fz} accumulators
__device__ float4 g_R4[MAX_ATOMS];    // packed positions, w unused

// Kernel 1: pack R into float4 and zero the accumulators (every replay).
__global__ void pack_zero_kernel(const float* __restrict__ R, int n_atoms) {
    int a = blockIdx.x * blockDim.x + threadIdx.x;
    if (a < n_atoms) {
        g_R4[a] = make_float4(__ldg(&R[3 * a + 0]),
                              __ldg(&R[3 * a + 1]),
                              __ldg(&R[3 * a + 2]), 0.0f);
        g_acc[a] = make_float4(0.0f, 0.0f, 0.0f, 0.0f);
    }
}

// Kernel 2: pair loop. Each thread owns 4 consecutive pairs (int4 idx loads).
__global__ void lj_pairs_kernel(const int* __restrict__ idx_i,
                                const int* __restrict__ idx_j,
                                const float* __restrict__ p_eps,
                                const float* __restrict__ p_sig,
                                const float* __restrict__ p_cut,
                                int n_pairs) {
    const float eps  = __ldg(p_eps);
    const float sig  = __ldg(p_sig);
    const float cut  = __ldg(p_cut);
    const float sig2 = sig * sig;
    const float cut2 = cut * cut;

    int t    = blockIdx.x * blockDim.x + threadIdx.x;
    int base = t * 4;
    if (base >= n_pairs) return;

    int ii[4], jj[4];
    if (base + 3 < n_pairs) {
        int4 vi = __ldg(reinterpret_cast<const int4*>(idx_i) + t);
        int4 vj = __ldg(reinterpret_cast<const int4*>(idx_j) + t);
        ii[0] = vi.x; ii[1] = vi.y; ii[2] = vi.z; ii[3] = vi.w;
        jj[0] = vj.x; jj[1] = vj.y; jj[2] = vj.z; jj[3] = vj.w;
    } else {
        #pragma unroll
        for (int k = 0; k < 4; k++) {
            int p = base + k;
            ii[k] = (p < n_pairs) ? __ldg(&idx_i[p]) : 0;
            jj[k] = (p < n_pairs) ? __ldg(&idx_j[p]) : 0;  // i==j -> masked out
        }
    }

    #pragma unroll
    for (int k = 0; k < 4; k++) {
        int p = base + k;
        if (p >= n_pairs) break;
        int i = ii[k];
        int j = jj[k];

        float4 Ri = __ldg(&g_R4[i]);
        float4 Rj = __ldg(&g_R4[j]);
        float dx = Ri.x - Rj.x;
        float dy = Ri.y - Rj.y;
        float dz = Ri.z - Rj.z;
        float r2 = fmaf(dx, dx, fmaf(dy, dy, dz * dz));

        if (r2 < cut2 && r2 > 1e-10f) {
            float inv  = __fdividef(1.0f, r2);
            float sr2  = sig2 * inv;
            float sr6  = sr2 * sr2 * sr2;
            float sr12 = sr6 * sr6;
            float e    = 4.0f * eps * (sr12 - sr6);
            float fm   = 24.0f * eps * fmaf(2.0f, sr12, -sr6) * inv;

            float* acc = reinterpret_cast<float*>(&g_acc[i]);
            atomicAdd(acc + 0, e);
            atomicAdd(acc + 1, fm * dx);
            atomicAdd(acc + 2, fm * dy);
            atomicAdd(acc + 3, fm * dz);
        }
    }
}

// Kernel 3: reshape accumulators into the output layout.
__global__ void writeout_kernel(float* __restrict__ out, int n_atoms) {
    int a = blockIdx.x * blockDim.x + threadIdx.x;
    if (a < n_atoms) {
        float4 v = g_acc[a];
        out[a] = 0.5f * v.x;                    // energy (0.5: symmetric list)
        float* f = out + n_atoms;
        f[3 * a + 0] = v.y;
        f[3 * a + 1] = v.z;
        f[3 * a + 2] = v.w;
    }
}

extern "C" void kernel_launch(void* const* d_in, const int* in_sizes, int n_in,
                              void* d_out, int out_size) {
    const float* R     = (const float*)d_in[0];
    const float* eps   = (const float*)d_in[1];
    const float* sig   = (const float*)d_in[2];
    const float* cut   = (const float*)d_in[3];
    const int*   idx_i = (const int*)d_in[4];
    const int*   idx_j = (const int*)d_in[5];
    float*       out   = (float*)d_out;

    int n_atoms = in_sizes[0] / 3;
    int n_pairs = in_sizes[4];

    const int T = 256;
    int blocks_atoms = (n_atoms + T - 1) / T;
    int n_groups     = (n_pairs + 3) / 4;            // 4 pairs per thread
    int blocks_pairs = (n_groups + T - 1) / T;

    pack_zero_kernel<<<blocks_atoms, T>>>(R, n_atoms);
    lj_pairs_kernel<<<blocks_pairs, T>>>(idx_i, idx_j, eps, sig, cut, n_pairs);
    writeout_kernel<<<blocks_atoms, T>>>(out, n_atoms);
}